// round 10
// baseline (speedup 1.0000x reference)
#include <cuda_runtime.h>
#include <cuda_bf16.h>
#include <math.h>
#include <stdint.h>

typedef unsigned long long ull;
#define FMA2(acc, a, b) asm("fma.rn.f32x2 %0, %1, %2, %0;" : "+l"(acc) : "l"(a), "l"(b))
__device__ __forceinline__ ull dupf(float x) { ull r; asm("mov.b64 %0, {%1, %1};" : "=l"(r) : "f"(x)); return r; }
__device__ __forceinline__ float2 u2f(ull v) { float2 r; asm("mov.b64 {%0, %1}, %2;" : "=f"(r.x), "=f"(r.y) : "l"(v)); return r; }
__device__ __forceinline__ uint32_t s2u(const void* p) {
    uint32_t a;
    asm("{.reg .u64 t; cvta.to.shared.u64 t, %1; cvt.u32.u64 %0, t;}" : "=r"(a) : "l"(p));
    return a;
}

// ------------------------- device-global scratch ---------------------------
__device__ float g_XW [(size_t)4096 * 4096];
__device__ float g_H  [(size_t)4096 * 1024];
__device__ float g_Up0[(size_t)1024 * 4096];
__device__ float g_Up1[(size_t)1024 * 4096];
__device__ float g_Zp [4 * 16 * 4096];
__device__ float g_h  [2][16 * 1024];
__device__ unsigned g_cnt, g_gen;
// bf16 hi/lo operand packs
__device__ __nv_bfloat16 g_Ah  [(size_t)4096  * 1024];
__device__ __nv_bfloat16 g_Al  [(size_t)4096  * 1024];
__device__ __nv_bfloat16 g_W0h [(size_t)4096  * 1024];
__device__ __nv_bfloat16 g_W0l [(size_t)4096  * 1024];
__device__ __nv_bfloat16 g_W1h [(size_t)4096  * 1024];
__device__ __nv_bfloat16 g_W1l [(size_t)4096  * 1024];
__device__ __nv_bfloat16 g_Woh [(size_t)32000 * 1024];
__device__ __nv_bfloat16 g_Wol [(size_t)32000 * 1024];

// Up[k][j][g] = U[k][g*1024+j]
__global__ void repack(const float* __restrict__ U, float* __restrict__ Up) {
    int i = blockIdx.x * 256 + threadIdx.x;
    int k = i >> 10, j = i & 1023;
    float4 v = { U[(size_t)k*4096 + j],        U[(size_t)k*4096 + 1024 + j],
                 U[(size_t)k*4096 + 2048 + j], U[(size_t)k*4096 + 3072 + j] };
    ((float4*)Up)[(size_t)k*1024 + j] = v;
}

// W[1024][N] -> Wh/Wl[N][1024] bf16 hi/lo (transpose via smem tile)
__global__ void repackW(const float* __restrict__ W,
                        __nv_bfloat16* __restrict__ Wh, __nv_bfloat16* __restrict__ Wl,
                        int N) {
    __shared__ float t[32][33];
    int kb = blockIdx.y * 32, nb = blockIdx.x * 32;
    int x = threadIdx.x, y = threadIdx.y;          // (32, 8)
#pragma unroll
    for (int i = 0; i < 4; i++)
        t[y + 8*i][x] = W[(size_t)(kb + y + 8*i) * N + nb + x];
    __syncthreads();
#pragma unroll
    for (int i = 0; i < 4; i++) {
        float v = t[x][y + 8*i];                   // k = kb+x, n = nb+y+8i
        __nv_bfloat16 h = __float2bfloat16(v);
        size_t o = (size_t)(nb + y + 8*i) * 1024 + kb + x;
        Wh[o] = h;
        Wl[o] = __float2bfloat16(v - __bfloat162float(h));
    }
}

// Xh/Xl[s][c] = bf16 hi/lo of emb[seq[s%16, s/16]][c] * 32
__global__ void gatherX(const int* __restrict__ seq, const float* __restrict__ emb,
                        __nv_bfloat16* __restrict__ Xh, __nv_bfloat16* __restrict__ Xl) {
    int s = blockIdx.x, c = threadIdx.x * 4;
    int tok = seq[(s & 15) * 256 + (s >> 4)];
    float4 v = *(const float4*)(emb + (size_t)tok * 1024 + c);
    v.x *= 32.f; v.y *= 32.f; v.z *= 32.f; v.w *= 32.f;
    float vv[4] = {v.x, v.y, v.z, v.w};
    size_t o = (size_t)s * 1024 + c;
#pragma unroll
    for (int i = 0; i < 4; i++) {
        __nv_bfloat16 h = __float2bfloat16(vv[i]);
        Xh[o + i] = h;
        Xl[o + i] = __float2bfloat16(vv[i] - __bfloat162float(h));
    }
}

// Hh/Hl = bf16 hi/lo of H
__global__ void convH(const float* __restrict__ H,
                      __nv_bfloat16* __restrict__ Hh, __nv_bfloat16* __restrict__ Hl) {
    int s = blockIdx.x, c = threadIdx.x * 4;
    float4 v = *(const float4*)(H + (size_t)s * 1024 + c);
    float vv[4] = {v.x, v.y, v.z, v.w};
    size_t o = (size_t)s * 1024 + c;
#pragma unroll
    for (int i = 0; i < 4; i++) {
        __nv_bfloat16 h = __float2bfloat16(vv[i]);
        Hh[o + i] = h;
        Hl[o + i] = __float2bfloat16(vv[i] - __bfloat162float(h));
    }
}

// ------------------------ tensor-core GEMM (HMMA) ---------------------------
// C[4096, N] = (Ah+Al) @ (Bh+Bl)^T + bias   via 3-pass bf16 hi/lo split.
// A: [4096][1024] bf16 row-major.  B: [N][1024] bf16 (i.e. B^T, k-contig).
// Block tile 128x128, BK=32, 8 warps (warp tile 32x64), cp.async 2-stage.
// cmode1: row s -> out[(s%16)*256 + s/16] remap (N=32000).
#define LDSM4(r, addr) \
    asm volatile("ldmatrix.sync.aligned.m8n8.x4.shared.b16 {%0,%1,%2,%3}, [%4];" \
        : "=r"((r)[0]), "=r"((r)[1]), "=r"((r)[2]), "=r"((r)[3]) : "r"(addr))
#define MMA(c, a, b0_, b1_) \
    asm volatile("mma.sync.aligned.m16n8k16.row.col.f32.bf16.bf16.f32 " \
        "{%0,%1,%2,%3},{%4,%5,%6,%7},{%8,%9},{%0,%1,%2,%3};" \
        : "+f"((c)[0]), "+f"((c)[1]), "+f"((c)[2]), "+f"((c)[3]) \
        : "r"((a)[0]), "r"((a)[1]), "r"((a)[2]), "r"((a)[3]), "r"(b0_), "r"(b1_))

#define GT_SMEM (2 * 4 * 10240)   // 2 stages x 4 tiles x 128 rows x 40 bf16

__global__ __launch_bounds__(256, 1)
void gemmT(const __nv_bfloat16* __restrict__ Ah, const __nv_bfloat16* __restrict__ Al,
           const __nv_bfloat16* __restrict__ Bh, const __nv_bfloat16* __restrict__ Bl,
           const float* __restrict__ bias, float* __restrict__ C, int N, int cmode)
{
    extern __shared__ char sm_[];
    const uint32_t sb = s2u(sm_);
    const int tid = threadIdx.x, lane = tid & 31, wid = tid >> 5;
    const int m0 = blockIdx.x * 128, n0 = blockIdx.y * 128;
    const int wm = (wid & 3) * 32, wn = (wid >> 2) * 64;

    const __nv_bfloat16* srcs[4] = {Ah, Al, Bh, Bl};
    const int lrow = tid >> 2, lseg = tid & 3;          // chunk 0; chunk 1 = +256

    // stage layout: +st*40960; tiles Ah:0 Al:10240 Bh:20480 Bl:30720; rows pad 40
    auto issue = [&](int st, int k0) {
        uint32_t base = sb + st * 40960u;
#pragma unroll
        for (int t4 = 0; t4 < 4; t4++) {
            int br = (t4 < 2) ? m0 : n0;
            const __nv_bfloat16* sp = srcs[t4];
#pragma unroll
            for (int i = 0; i < 2; i++) {
                int row = lrow + i * 64, seg = lseg;
                uint32_t dst = base + t4 * 10240u + row * 80u + seg * 16u;
                const void* src = sp + (size_t)(br + row) * 1024 + k0 + seg * 8;
                asm volatile("cp.async.cg.shared.global [%0], [%1], 16;"
                             :: "r"(dst), "l"(src));
            }
        }
    };

    // ldmatrix per-lane address bases (bytes, within stage)
    const uint32_t aAddr = sb + (wm + (lane & 15)) * 80u + (lane >> 4) * 16u;
    const uint32_t bAddr = sb + 20480u
        + (wn + (lane & 7) + ((lane >> 4) & 1) * 8) * 80u + ((lane >> 3) & 1) * 16u;

    float acc[2][8][4];
#pragma unroll
    for (int mt = 0; mt < 2; mt++)
#pragma unroll
        for (int n = 0; n < 8; n++)
#pragma unroll
            for (int q = 0; q < 4; q++) acc[mt][n][q] = 0.f;

    issue(0, 0);
    asm volatile("cp.async.commit_group;");

    for (int it = 0; it < 32; it++) {
        if (it < 31) {
            issue((it + 1) & 1, (it + 1) * 32);
            asm volatile("cp.async.commit_group;");
            asm volatile("cp.async.wait_group 1;");
        } else {
            asm volatile("cp.async.wait_group 0;");
        }
        __syncthreads();
        uint32_t st = (it & 1) * 40960u;
#pragma unroll
        for (int ks = 0; ks < 2; ks++) {
            uint32_t ao = aAddr + st + ks * 32u, bo = bAddr + st + ks * 32u;
            uint32_t ah[2][4], al_[2][4], bh[4][4], bl_[4][4];
            LDSM4(ah[0], ao);            LDSM4(ah[1], ao + 1280u);
            LDSM4(al_[0], ao + 10240u);  LDSM4(al_[1], ao + 11520u);
#pragma unroll
            for (int nt = 0; nt < 4; nt++) {
                LDSM4(bh[nt],  bo + nt * 1280u);
                LDSM4(bl_[nt], bo + 10240u + nt * 1280u);
            }
#pragma unroll
            for (int mt = 0; mt < 2; mt++)
#pragma unroll
                for (int n = 0; n < 8; n++) {
                    uint32_t b0h = bh[n >> 1][(n & 1) * 2], b1h = bh[n >> 1][(n & 1) * 2 + 1];
                    uint32_t b0l = bl_[n >> 1][(n & 1) * 2], b1l = bl_[n >> 1][(n & 1) * 2 + 1];
                    MMA(acc[mt][n], ah[mt], b0h, b1h);
                    MMA(acc[mt][n], ah[mt], b0l, b1l);
                    MMA(acc[mt][n], al_[mt], b0h, b1h);
                }
        }
        __syncthreads();
    }

    // epilogue: c0,c1 -> row g, cols tig*2..+1; c2,c3 -> row g+8
    const int g = lane >> 2, tig = lane & 3;
#pragma unroll
    for (int mt = 0; mt < 2; mt++)
#pragma unroll
        for (int n = 0; n < 8; n++) {
            int col = n0 + wn + n * 8 + tig * 2;
            float2 bi = *(const float2*)(bias + col);
            int r0 = m0 + wm + mt * 16 + g, r1 = r0 + 8;
            size_t o0, o1;
            if (cmode) {
                o0 = (size_t)(r0 & 15) * 8192000u + (size_t)(r0 >> 4) * 32000u + col;
                o1 = (size_t)(r1 & 15) * 8192000u + (size_t)(r1 >> 4) * 32000u + col;
            } else {
                o0 = (size_t)r0 * N + col;
                o1 = (size_t)r1 * N + col;
            }
            float2 v0 = { acc[mt][n][0] + bi.x, acc[mt][n][1] + bi.y };
            float2 v1 = { acc[mt][n][2] + bi.x, acc[mt][n][3] + bi.y };
            *(float2*)(C + o0) = v0;
            *(float2*)(C + o1) = v1;
        }
}

// ----------------------------- grid barrier ---------------------------------
#define NBLK 128u
__device__ __forceinline__ void gbar() {
    __syncthreads();
    if (threadIdx.x == 0) {
        unsigned gen, a;
        asm volatile("ld.acquire.gpu.global.u32 %0, [%1];" : "=r"(gen) : "l"(&g_gen));
        asm volatile("atom.release.gpu.global.add.u32 %0, [%1], %2;"
                     : "=r"(a) : "l"(&g_cnt), "r"(1u));
        if (a == NBLK - 1u) {
            asm volatile("st.relaxed.gpu.global.u32 [%0], %1;" :: "l"(&g_cnt), "r"(0u));
            asm volatile("red.release.gpu.global.add.u32 [%0], %1;" :: "l"(&g_gen), "r"(1u));
        } else {
            unsigned c;
            do { asm volatile("ld.acquire.gpu.global.u32 %0, [%1];" : "=r"(c) : "l"(&g_gen)); }
            while (c == gen);
        }
    }
    __syncthreads();
}

// ----------------------- persistent LSTM layer ------------------------------
#define SMEM_LSTM (131072 + 256 * 20 * 4)
__global__ __launch_bounds__(128, 1)
void lstm_layer(const float4* __restrict__ Up, const float* __restrict__ XW,
                float* __restrict__ H)
{
    extern __shared__ char sm_[];
    float4* up_s = (float4*)sm_;                          // [256][32] = 128KB
    float (*hs)[20] = (float(*)[20])(sm_ + 131072);       // [256][20]

    const int tid = threadIdx.x, bl = blockIdx.x;
    const int jc = bl & 31, kc = bl >> 5, k0 = kc * 256;
    const int jj = tid >> 2, bg = tid & 3;
    const int gi = bl * 128 + tid, bB = gi >> 10, jB = gi & 1023;

    {
        const float4* up = Up + (size_t)k0 * 1024 + jc * 32;
#pragma unroll 8
        for (int i = tid; i < 8192; i += 128)
            up_s[i] = up[(size_t)(i >> 5) * 1024 + (i & 31)];
    }
    g_h[0][gi] = 0.f;
    float creg = 0.f;
    gbar();

    for (int t = 0; t < 256; t++) {
        const float* hsrc = g_h[t & 1];
#pragma unroll
        for (int r = 0; r < 8; r++) {
            int idx = r * 128 + tid, b = idx >> 6, q = idx & 63;
            float4 v = __ldcg((const float4*)(hsrc + b * 1024 + k0) + q);
            hs[q*4+0][b] = v.x; hs[q*4+1][b] = v.y; hs[q*4+2][b] = v.z; hs[q*4+3][b] = v.w;
        }
        __syncthreads();
        ull acc[4][2];
#pragma unroll
        for (int g = 0; g < 4; g++) { acc[g][0] = 0ull; acc[g][1] = 0ull; }
        const float4* ups = up_s + jj;
#pragma unroll 8
        for (int kk = 0; kk < 256; kk++) {
            float4 u  = ups[kk * 32];
            float4 hv = *(float4*)&hs[kk][bg * 4];
            ull h2a = ((ull*)&hv)[0], h2b = ((ull*)&hv)[1];
            ull a0 = dupf(u.x), a1 = dupf(u.y), a2 = dupf(u.z), a3 = dupf(u.w);
            FMA2(acc[0][0], a0, h2a); FMA2(acc[0][1], a0, h2b);
            FMA2(acc[1][0], a1, h2a); FMA2(acc[1][1], a1, h2b);
            FMA2(acc[2][0], a2, h2a); FMA2(acc[2][1], a2, h2b);
            FMA2(acc[3][0], a3, h2a); FMA2(acc[3][1], a3, h2b);
        }
        const int j = jc * 32 + jj;
#pragma unroll
        for (int g = 0; g < 4; g++) {
            float2 v0 = u2f(acc[g][0]), v1 = u2f(acc[g][1]);
            int base = kc * 65536 + g * 1024 + j;
            g_Zp[base + (bg*4+0) * 4096] = v0.x;
            g_Zp[base + (bg*4+1) * 4096] = v0.y;
            g_Zp[base + (bg*4+2) * 4096] = v1.x;
            g_Zp[base + (bg*4+3) * 4096] = v1.y;
        }
        gbar();
        int s = t * 16 + bB;
        float z[4];
#pragma unroll
        for (int g = 0; g < 4; g++) {
            int col = g * 1024 + jB;
            float v = XW[(size_t)s * 4096 + col];
#pragma unroll
            for (int p = 0; p < 4; p++) v += __ldcg(&g_Zp[p * 65536 + bB * 4096 + col]);
            z[g] = v;
        }
        float i_ = 1.f / (1.f + expf(-z[0]));
        float f_ = 1.f / (1.f + expf(-z[1]));
        float o_ = 1.f / (1.f + expf(-z[3]));
        creg = f_ * creg + i_ * tanhf(z[2]);
        float hn = o_ * tanhf(creg);
        g_h[(t + 1) & 1][bB * 1024 + jB] = hn;
        H[(size_t)s * 1024 + jB] = hn;
        gbar();
    }
}

// ---------------------------------------------------------------------------
extern "C" void kernel_launch(void* const* d_in, const int* in_sizes, int n_in,
                              void* d_out, int out_size)
{
    const int*   seq  = (const int*)  d_in[0];
    const float* emb  = (const float*)d_in[1];
    const float* W0   = (const float*)d_in[2];
    const float* U0   = (const float*)d_in[3];
    const float* b0   = (const float*)d_in[4];
    const float* W1   = (const float*)d_in[5];
    const float* U1   = (const float*)d_in[6];
    const float* b1   = (const float*)d_in[7];
    const float* Wout = (const float*)d_in[8];
    const float* bout = (const float*)d_in[9];
    float* out = (float*)d_out;

    float *XW, *H, *Up0, *Up1;
    __nv_bfloat16 *Ah, *Al, *W0h, *W0l, *W1h, *W1l, *Woh, *Wol;
    cudaGetSymbolAddress((void**)&XW,  g_XW);
    cudaGetSymbolAddress((void**)&H,   g_H);
    cudaGetSymbolAddress((void**)&Up0, g_Up0);
    cudaGetSymbolAddress((void**)&Up1, g_Up1);
    cudaGetSymbolAddress((void**)&Ah,  g_Ah);
    cudaGetSymbolAddress((void**)&Al,  g_Al);
    cudaGetSymbolAddress((void**)&W0h, g_W0h);
    cudaGetSymbolAddress((void**)&W0l, g_W0l);
    cudaGetSymbolAddress((void**)&W1h, g_W1h);
    cudaGetSymbolAddress((void**)&W1l, g_W1l);
    cudaGetSymbolAddress((void**)&Woh, g_Woh);
    cudaGetSymbolAddress((void**)&Wol, g_Wol);

    cudaFuncSetAttribute(lstm_layer, cudaFuncAttributeMaxDynamicSharedMemorySize, SMEM_LSTM);
    cudaFuncSetAttribute(gemmT, cudaFuncAttributeMaxDynamicSharedMemorySize, GT_SMEM);

    repack<<<4096, 256>>>(U0, Up0);
    repack<<<4096, 256>>>(U1, Up1);
    repackW<<<dim3(128, 32),  dim3(32, 8)>>>(W0,   W0h, W0l, 4096);
    repackW<<<dim3(128, 32),  dim3(32, 8)>>>(W1,   W1h, W1l, 4096);
    repackW<<<dim3(1000, 32), dim3(32, 8)>>>(Wout, Woh, Wol, 32000);
    gatherX<<<4096, 256>>>(seq, emb, Ah, Al);

    gemmT<<<dim3(32, 32), 256, GT_SMEM>>>(Ah, Al, W0h, W0l, b0, XW, 4096, 0);
    lstm_layer<<<128, 128, SMEM_LSTM>>>((const float4*)Up0, XW, H);
    convH<<<4096, 256>>>(H, Ah, Al);
    gemmT<<<dim3(32, 32), 256, GT_SMEM>>>(Ah, Al, W1h, W1l, b1, XW, 4096, 0);
    lstm_layer<<<128, 128, SMEM_LSTM>>>((const float4*)Up1, XW, H);
    convH<<<4096, 256>>>(H, Ah, Al);
    gemmT<<<dim3(32, 250), 256, GT_SMEM>>>(Ah, Al, Woh, Wol, bout, out, 32000, 1);
}

// round 11
// speedup vs baseline: 1.0727x; 1.0727x over previous
#include <cuda_runtime.h>
#include <cuda_bf16.h>
#include <math.h>
#include <stdint.h>

typedef unsigned long long ull;
#define FMA2(acc, a, b) asm("fma.rn.f32x2 %0, %1, %2, %0;" : "+l"(acc) : "l"(a), "l"(b))
__device__ __forceinline__ ull dupf(float x) { ull r; asm("mov.b64 %0, {%1, %1};" : "=l"(r) : "f"(x)); return r; }
__device__ __forceinline__ float2 u2f(ull v) { float2 r; asm("mov.b64 {%0, %1}, %2;" : "=f"(r.x), "=f"(r.y) : "l"(v)); return r; }

// ------------------------- device-global scratch ---------------------------
__device__ float g_XW [(size_t)4096 * 4096];   // x@W + b (both layers, reused)
__device__ float g_H  [(size_t)4096 * 1024];   // hidden history
__device__ float g_Up0[(size_t)1024 * 4096];   // gate-interleaved U0
__device__ float g_Up1[(size_t)1024 * 4096];
__device__ float g_h  [2][16 * 1024];          // double-buffered h
__device__ unsigned g_cnt, g_gen;

// Up[k][j][g] = U[k][g*1024+j]  (float4 over gates)
__global__ void repack(const float* __restrict__ U, float* __restrict__ Up) {
    int i = blockIdx.x * 256 + threadIdx.x;
    int k = i >> 10, j = i & 1023;
    float4 v = { U[(size_t)k*4096 + j],        U[(size_t)k*4096 + 1024 + j],
                 U[(size_t)k*4096 + 2048 + j], U[(size_t)k*4096 + 3072 + j] };
    ((float4*)Up)[(size_t)k*1024 + j] = v;
}

// --------------------------- f32x2 GEMM -------------------------------------
// C[4096, N] = A @ Bm[1024, N] + bias.  128x128x16 tiles, 8x8/thr via FFMA2.
// grid (x = m-tiles, y = n-tiles): concurrent waves share B panels, A stays L2-hot.
// amode1: row s <- emb[seq[s%16, s/16]]*32.
// cmode1: row s -> out[(s%16)*256 + s/16] remap.
__global__ __launch_bounds__(256, 2)
void gemm(const float* __restrict__ A, const float* __restrict__ Bm,
          const float* __restrict__ bias, float* __restrict__ C,
          int N, int amode, int cmode,
          const int* __restrict__ seq, const float* __restrict__ emb)
{
    __shared__ float As[16][128];
    __shared__ float Bs[16][128];
    int tid = threadIdx.x;
    int m0 = blockIdx.x * 128, n0 = blockIdx.y * 128;
    int ty = tid >> 4, tx = tid & 15;
    ull acc[8][4];
#pragma unroll
    for (int i = 0; i < 8; i++)
#pragma unroll
        for (int j = 0; j < 4; j++) acc[i][j] = 0ull;

    for (int k0 = 0; k0 < 1024; k0 += 16) {
#pragma unroll
        for (int i = 0; i < 2; i++) {                        // A tile, transposed
            int q = tid + i * 256, row = q >> 2, kc = (q & 3) * 4, s = m0 + row;
            float4 v;
            if (amode) {
                int tok = seq[(s & 15) * 256 + (s >> 4)];
                v = *(const float4*)(emb + (size_t)tok * 1024 + k0 + kc);
                v.x *= 32.f; v.y *= 32.f; v.z *= 32.f; v.w *= 32.f;
            } else {
                v = *(const float4*)(A + (size_t)s * 1024 + k0 + kc);
            }
            As[kc][row] = v.x; As[kc+1][row] = v.y; As[kc+2][row] = v.z; As[kc+3][row] = v.w;
        }
#pragma unroll
        for (int i = 0; i < 2; i++) {                        // B tile
            int q = tid + i * 256, kr = q >> 5, col = (q & 31) * 4;
            *(float4*)&Bs[kr][col] = *(const float4*)(Bm + (size_t)(k0 + kr) * N + n0 + col);
        }
        __syncthreads();
#pragma unroll
        for (int kk = 0; kk < 16; kk++) {
            float ra[8]; ull rb[4];
            *(float4*)ra       = *(float4*)&As[kk][ty * 8];
            *(float4*)(ra + 4) = *(float4*)&As[kk][ty * 8 + 4];
            float4 b0_ = *(float4*)&Bs[kk][tx * 8];
            float4 b1_ = *(float4*)&Bs[kk][tx * 8 + 4];
            rb[0] = ((ull*)&b0_)[0]; rb[1] = ((ull*)&b0_)[1];
            rb[2] = ((ull*)&b1_)[0]; rb[3] = ((ull*)&b1_)[1];
#pragma unroll
            for (int i = 0; i < 8; i++) {
                ull a2 = dupf(ra[i]);
                FMA2(acc[i][0], a2, rb[0]); FMA2(acc[i][1], a2, rb[1]);
                FMA2(acc[i][2], a2, rb[2]); FMA2(acc[i][3], a2, rb[3]);
            }
        }
        __syncthreads();
    }
    float bi[8];
#pragma unroll
    for (int j = 0; j < 8; j++) bi[j] = bias[n0 + tx * 8 + j];
#pragma unroll
    for (int i = 0; i < 8; i++) {
        int s = m0 + ty * 8 + i;
        size_t off = cmode
            ? (size_t)(s & 15) * 8192000u + (size_t)(s >> 4) * 32000u + n0 + tx * 8
            : (size_t)s * N + n0 + tx * 8;
        float c_[8];
#pragma unroll
        for (int jp = 0; jp < 4; jp++) {
            float2 v = u2f(acc[i][jp]);
            c_[jp*2] = v.x + bi[jp*2]; c_[jp*2+1] = v.y + bi[jp*2+1];
        }
        *(float4*)(C + off)     = *(float4*)c_;
        *(float4*)(C + off + 4) = *(float4*)(c_ + 4);
    }
}

// ----------------------------- grid barrier ---------------------------------
#define NBLK 128u
__device__ __forceinline__ void gbar() {
    __syncthreads();
    if (threadIdx.x == 0) {
        unsigned gen, a;
        asm volatile("ld.acquire.gpu.global.u32 %0, [%1];" : "=r"(gen) : "l"(&g_gen));
        asm volatile("atom.release.gpu.global.add.u32 %0, [%1], %2;"
                     : "=r"(a) : "l"(&g_cnt), "r"(1u));
        if (a == NBLK - 1u) {
            asm volatile("st.relaxed.gpu.global.u32 [%0], %1;" :: "l"(&g_cnt), "r"(0u));
            asm volatile("red.release.gpu.global.add.u32 [%0], %1;" :: "l"(&g_gen), "r"(1u));
        } else {
            unsigned c;
            do { asm volatile("ld.acquire.gpu.global.u32 %0, [%1];" : "=r"(c) : "l"(&g_gen)); }
            while (c == gen);
        }
    }
    __syncthreads();
}

// ----------------- fused persistent LSTM layer (ONE gbar/step) --------------
// 128 blocks x 128 threads. Block bl owns j in [bl*8, bl*8+8), ALL 4 gates,
// 16 batches, full k=1024 (k split 4-ways across warps, reduced in smem).
// smem: up_s [1024k][8j] float4(gates) = 128KB;  hs [1024k][20] = 80KB (pad
// 20 keeps stores conflict-free and float4 reads aligned);  red 8KB.
#define SM_UP 0
#define SM_HS 131072
#define SM_RED (131072 + 81920)
#define SMEM_LSTM (131072 + 81920 + 8192)
__global__ __launch_bounds__(128, 1)
void lstm_fused(const float4* __restrict__ Up, const float* __restrict__ XW,
                float* __restrict__ H)
{
    extern __shared__ char sm_[];
    float4* up_s = (float4*)(sm_ + SM_UP);       // [k][jj]
    float*  hs   = (float*) (sm_ + SM_HS);       // [k][20], h at [k][b]
    float4* red  = (float4*)(sm_ + SM_RED);      // [kq][b][jj] gates-float4

    const int tid = threadIdx.x, bl = blockIdx.x;
    const int w = tid >> 5, lane = tid & 31;     // w = k-quarter
    const int jj = (tid & 31) >> 2, bg = tid & 3;// compute identity (per warp)
    const int sbB = lane >> 1, kg = lane & 1;    // staging identity
    const int bR = tid >> 3, jR = tid & 7;       // reducer identity
    const int jRg = bl * 8 + jR;

    // one-time: stage Up slice [1024][8] gate-float4
    {
        const float4* up = Up + bl * 8;
#pragma unroll 8
        for (int i = tid; i < 8192; i += 128)
            up_s[i] = up[(size_t)(i >> 3) * 1024 + (i & 7)];
    }
    g_h[0][bl * 128 + tid] = 0.f;
    float creg = 0.f;
    gbar();

    for (int t = 0; t < 256; t++) {
        // prefetch XW gate values for reducer identity (hides under compute)
        float xw[4];
        {
            const float* xp = XW + (size_t)(t * 16 + bR) * 4096 + jRg;
#pragma unroll
            for (int g = 0; g < 4; g++) xw[g] = __ldcg(xp + g * 1024);
        }
        // stage h[16][1024] -> hs[k][b]; lanes (b=sbB, kg) -> conflict-free
        {
            const float4* hsrc = (const float4*)g_h[t & 1] + sbB * 256;
#pragma unroll
            for (int i = 0; i < 32; i++) {
                int k4 = i * 8 + w * 2 + kg;
                float4 v = __ldcg(hsrc + k4);
                float* d = hs + (k4 * 4) * 20 + sbB;
                d[0] = v.x; d[20] = v.y; d[40] = v.z; d[60] = v.w;
            }
        }
        __syncthreads();
        // compute: thread (w, jj, bg): j = bl*8+jj, gates 0..3, b = bg*4..+3,
        // k in [w*256, +256)
        ull acc[4][2];
#pragma unroll
        for (int g = 0; g < 4; g++) { acc[g][0] = 0ull; acc[g][1] = 0ull; }
        const float4* up = up_s + w * 256 * 8 + jj;
        const float*  hp = hs + w * 256 * 20 + bg * 4;
#pragma unroll 8
        for (int kk = 0; kk < 256; kk++) {
            float4 u  = up[kk * 8];
            float4 hv = *(const float4*)(hp + kk * 20);
            ull h2a = ((ull*)&hv)[0], h2b = ((ull*)&hv)[1];
            ull a0 = dupf(u.x), a1 = dupf(u.y), a2 = dupf(u.z), a3 = dupf(u.w);
            FMA2(acc[0][0], a0, h2a); FMA2(acc[0][1], a0, h2b);
            FMA2(acc[1][0], a1, h2a); FMA2(acc[1][1], a1, h2b);
            FMA2(acc[2][0], a2, h2a); FMA2(acc[2][1], a2, h2b);
            FMA2(acc[3][0], a3, h2a); FMA2(acc[3][1], a3, h2b);
        }
        // partials -> red[w][b][jj] as gate-float4
        {
            float2 p[4][2];
#pragma unroll
            for (int g = 0; g < 4; g++) { p[g][0] = u2f(acc[g][0]); p[g][1] = u2f(acc[g][1]); }
#pragma unroll
            for (int i = 0; i < 4; i++) {
                int b = bg * 4 + i;
                float4 zv;
                zv.x = (i & 1) ? p[0][i >> 1].y : p[0][i >> 1].x;
                zv.y = (i & 1) ? p[1][i >> 1].y : p[1][i >> 1].x;
                zv.z = (i & 1) ? p[2][i >> 1].y : p[2][i >> 1].x;
                zv.w = (i & 1) ? p[3][i >> 1].y : p[3][i >> 1].x;
                red[(w * 16 + b) * 8 + jj] = zv;
            }
        }
        __syncthreads();
        // reduce over 4 k-quarters + gates; thread (bR, jR)
        {
            float4 r0 = red[(0  + bR) * 8 + jR];
            float4 r1 = red[(16 + bR) * 8 + jR];
            float4 r2 = red[(32 + bR) * 8 + jR];
            float4 r3 = red[(48 + bR) * 8 + jR];
            float z0 = xw[0] + r0.x + r1.x + r2.x + r3.x;
            float z1 = xw[1] + r0.y + r1.y + r2.y + r3.y;
            float z2 = xw[2] + r0.z + r1.z + r2.z + r3.z;
            float z3 = xw[3] + r0.w + r1.w + r2.w + r3.w;
            float i_ = 1.f / (1.f + expf(-z0));
            float f_ = 1.f / (1.f + expf(-z1));
            float o_ = 1.f / (1.f + expf(-z3));
            creg = f_ * creg + i_ * tanhf(z2);
            float hn = o_ * tanhf(creg);
            __stcg(&g_h[(t + 1) & 1][bR * 1024 + jRg], hn);
            __stcg(&H[(size_t)(t * 16 + bR) * 1024 + jRg], hn);
        }
        gbar();
    }
}

// ---------------------------------------------------------------------------
extern "C" void kernel_launch(void* const* d_in, const int* in_sizes, int n_in,
                              void* d_out, int out_size)
{
    const int*   seq  = (const int*)  d_in[0];
    const float* emb  = (const float*)d_in[1];
    const float* W0   = (const float*)d_in[2];
    const float* U0   = (const float*)d_in[3];
    const float* b0   = (const float*)d_in[4];
    const float* W1   = (const float*)d_in[5];
    const float* U1   = (const float*)d_in[6];
    const float* b1   = (const float*)d_in[7];
    const float* Wout = (const float*)d_in[8];
    const float* bout = (const float*)d_in[9];
    float* out = (float*)d_out;

    float *XW, *H, *Up0, *Up1;
    cudaGetSymbolAddress((void**)&XW,  g_XW);
    cudaGetSymbolAddress((void**)&H,   g_H);
    cudaGetSymbolAddress((void**)&Up0, g_Up0);
    cudaGetSymbolAddress((void**)&Up1, g_Up1);

    cudaFuncSetAttribute(lstm_fused, cudaFuncAttributeMaxDynamicSharedMemorySize, SMEM_LSTM);

    repack<<<4096, 256>>>(U0, Up0);
    repack<<<4096, 256>>>(U1, Up1);

    gemm<<<dim3(32, 32), 256>>>(nullptr, W0, b0, XW, 4096, 1, 0, seq, emb);
    lstm_fused<<<128, 128, SMEM_LSTM>>>((const float4*)Up0, XW, H);
    gemm<<<dim3(32, 32), 256>>>(H, W1, b1, XW, 4096, 0, 0, nullptr, nullptr);
    lstm_fused<<<128, 128, SMEM_LSTM>>>((const float4*)Up1, XW, H);
    gemm<<<dim3(32, 250), 256>>>(H, Wout, bout, out, 32000, 0, 1, nullptr, nullptr);
}

// round 12
// speedup vs baseline: 1.0774x; 1.0044x over previous
#include <cuda_runtime.h>
#include <cuda_bf16.h>
#include <math.h>
#include <stdint.h>

typedef unsigned long long ull;
#define FMA2(acc, a, b) asm("fma.rn.f32x2 %0, %1, %2, %0;" : "+l"(acc) : "l"(a), "l"(b))
__device__ __forceinline__ ull dupf(float x) { ull r; asm("mov.b64 %0, {%1, %1};" : "=l"(r) : "f"(x)); return r; }
__device__ __forceinline__ float2 u2f(ull v) { float2 r; asm("mov.b64 {%0, %1}, %2;" : "=f"(r.x), "=f"(r.y) : "l"(v)); return r; }

// ------------------------- device-global scratch ---------------------------
__device__ float g_XW [(size_t)4096 * 4096];   // x@W + b (both layers, reused)
__device__ float g_H  [(size_t)4096 * 1024];   // hidden history
__device__ float g_Up0[(size_t)1024 * 4096];   // gate-interleaved U0
__device__ float g_Up1[(size_t)1024 * 4096];
__device__ float g_h  [2][16 * 1024];          // double-buffered h
__device__ unsigned g_cnt, g_gen;

// Up[k][j][g] = U[k][g*1024+j]  (float4 over gates)
__global__ void repack(const float* __restrict__ U, float* __restrict__ Up) {
    int i = blockIdx.x * 256 + threadIdx.x;
    int k = i >> 10, j = i & 1023;
    float4 v = { U[(size_t)k*4096 + j],        U[(size_t)k*4096 + 1024 + j],
                 U[(size_t)k*4096 + 2048 + j], U[(size_t)k*4096 + 3072 + j] };
    ((float4*)Up)[(size_t)k*1024 + j] = v;
}

// --------------------------- f32x2 GEMM -------------------------------------
// C[4096, N] = A @ Bm[1024, N] + bias.  128x128x16 tiles, 8x8/thr via FFMA2.
// amode1: row s <- emb[seq[s%16, s/16]]*32.
// cmode1: row s -> out[(s%16)*256 + s/16] remap.
__global__ __launch_bounds__(256, 2)
void gemm(const float* __restrict__ A, const float* __restrict__ Bm,
          const float* __restrict__ bias, float* __restrict__ C,
          int N, int amode, int cmode,
          const int* __restrict__ seq, const float* __restrict__ emb)
{
    __shared__ float As[16][128];
    __shared__ float Bs[16][128];
    int tid = threadIdx.x;
    int m0 = blockIdx.x * 128, n0 = blockIdx.y * 128;
    int ty = tid >> 4, tx = tid & 15;
    ull acc[8][4];
#pragma unroll
    for (int i = 0; i < 8; i++)
#pragma unroll
        for (int j = 0; j < 4; j++) acc[i][j] = 0ull;

    for (int k0 = 0; k0 < 1024; k0 += 16) {
#pragma unroll
        for (int i = 0; i < 2; i++) {                        // A tile, transposed
            int q = tid + i * 256, row = q >> 2, kc = (q & 3) * 4, s = m0 + row;
            float4 v;
            if (amode) {
                int tok = seq[(s & 15) * 256 + (s >> 4)];
                v = *(const float4*)(emb + (size_t)tok * 1024 + k0 + kc);
                v.x *= 32.f; v.y *= 32.f; v.z *= 32.f; v.w *= 32.f;
            } else {
                v = *(const float4*)(A + (size_t)s * 1024 + k0 + kc);
            }
            As[kc][row] = v.x; As[kc+1][row] = v.y; As[kc+2][row] = v.z; As[kc+3][row] = v.w;
        }
#pragma unroll
        for (int i = 0; i < 2; i++) {                        // B tile
            int q = tid + i * 256, kr = q >> 5, col = (q & 31) * 4;
            *(float4*)&Bs[kr][col] = *(const float4*)(Bm + (size_t)(k0 + kr) * N + n0 + col);
        }
        __syncthreads();
#pragma unroll
        for (int kk = 0; kk < 16; kk++) {
            float ra[8]; ull rb[4];
            *(float4*)ra       = *(float4*)&As[kk][ty * 8];
            *(float4*)(ra + 4) = *(float4*)&As[kk][ty * 8 + 4];
            float4 b0_ = *(float4*)&Bs[kk][tx * 8];
            float4 b1_ = *(float4*)&Bs[kk][tx * 8 + 4];
            rb[0] = ((ull*)&b0_)[0]; rb[1] = ((ull*)&b0_)[1];
            rb[2] = ((ull*)&b1_)[0]; rb[3] = ((ull*)&b1_)[1];
#pragma unroll
            for (int i = 0; i < 8; i++) {
                ull a2 = dupf(ra[i]);
                FMA2(acc[i][0], a2, rb[0]); FMA2(acc[i][1], a2, rb[1]);
                FMA2(acc[i][2], a2, rb[2]); FMA2(acc[i][3], a2, rb[3]);
            }
        }
        __syncthreads();
    }
    float bi[8];
#pragma unroll
    for (int j = 0; j < 8; j++) bi[j] = bias[n0 + tx * 8 + j];
#pragma unroll
    for (int i = 0; i < 8; i++) {
        int s = m0 + ty * 8 + i;
        size_t off = cmode
            ? (size_t)(s & 15) * 8192000u + (size_t)(s >> 4) * 32000u + n0 + tx * 8
            : (size_t)s * N + n0 + tx * 8;
        float c_[8];
#pragma unroll
        for (int jp = 0; jp < 4; jp++) {
            float2 v = u2f(acc[i][jp]);
            c_[jp*2] = v.x + bi[jp*2]; c_[jp*2+1] = v.y + bi[jp*2+1];
        }
        *(float4*)(C + off)     = *(float4*)c_;
        *(float4*)(C + off + 4) = *(float4*)(c_ + 4);
    }
}

// ----------------------------- grid barrier ---------------------------------
#define NBLK 128u
__device__ __forceinline__ void gbar() {
    __syncthreads();
    if (threadIdx.x == 0) {
        unsigned gen, a;
        asm volatile("ld.acquire.gpu.global.u32 %0, [%1];" : "=r"(gen) : "l"(&g_gen));
        asm volatile("atom.release.gpu.global.add.u32 %0, [%1], %2;"
                     : "=r"(a) : "l"(&g_cnt), "r"(1u));
        if (a == NBLK - 1u) {
            asm volatile("st.relaxed.gpu.global.u32 [%0], %1;" :: "l"(&g_cnt), "r"(0u));
            asm volatile("red.release.gpu.global.add.u32 [%0], %1;" :: "l"(&g_gen), "r"(1u));
        } else {
            unsigned c;
            do { asm volatile("ld.acquire.gpu.global.u32 %0, [%1];" : "=r"(c) : "l"(&g_gen)); }
            while (c == gen);
        }
    }
    __syncthreads();
}

// ----------------- fused persistent LSTM layer (256 thr: 2 warps/SMSP) ------
// 128 blocks x 256 threads. Block bl owns j in [bl*8, bl*8+8), all 4 gates,
// 16 batches, full k=1024 split 8 ways across warps, reduced in smem.
// smem: up_s [1024k][8j] float4(gates) = 128KB;  hs [1024k][20] = 80KB;
// red [8kq][16b][8j] float4 = 16KB.  Total 224KB.
#define SM_UP 0
#define SM_HS 131072
#define SM_RED (131072 + 81920)
#define SMEM_LSTM (131072 + 81920 + 16384)
__global__ __launch_bounds__(256, 1)
void lstm_fused(const float4* __restrict__ Up, const float* __restrict__ XW,
                float* __restrict__ H)
{
    extern __shared__ char sm_[];
    float4* up_s = (float4*)(sm_ + SM_UP);       // [k][jj]
    float*  hs   = (float*) (sm_ + SM_HS);       // [k][20], h at [k][b]
    float4* red  = (float4*)(sm_ + SM_RED);      // [kq][b][jj] gates-float4

    const int tid = threadIdx.x, bl = blockIdx.x;
    const int w = tid >> 5, lane = tid & 31;     // w = k-eighth (0..7)
    const int jj = (tid & 31) >> 2, bg = tid & 3;// compute identity (per warp)
    const int sbB = lane >> 1, kg = lane & 1;    // staging identity
    const int bR = (tid & 127) >> 3, jR = tid & 7; // reducer identity (tid<128)
    const int jRg = bl * 8 + jR;

    // one-time: stage Up slice [1024][8] gate-float4
    {
        const float4* up = Up + bl * 8;
#pragma unroll 8
        for (int i = tid; i < 8192; i += 256)
            up_s[i] = up[(size_t)(i >> 3) * 1024 + (i & 7)];
    }
    if (tid < 128) g_h[0][bl * 128 + tid] = 0.f;
    float creg = 0.f;
    gbar();

    for (int t = 0; t < 256; t++) {
        // prefetch XW gate values (reducer threads only; hides under compute)
        float xw[4];
        if (tid < 128) {
            const float* xp = XW + (size_t)(t * 16 + bR) * 4096 + jRg;
#pragma unroll
            for (int g = 0; g < 4; g++) xw[g] = __ldcg(xp + g * 1024);
        }
        // stage h[16][1024] -> hs[k][b]; (sbB, kg) layout is bank-conflict-free
        {
            const float4* hsrc = (const float4*)g_h[t & 1] + sbB * 256;
#pragma unroll
            for (int i = 0; i < 16; i++) {
                int k4 = i * 16 + w * 2 + kg;
                float4 v = __ldcg(hsrc + k4);
                float* d = hs + (k4 * 4) * 20 + sbB;
                d[0] = v.x; d[20] = v.y; d[40] = v.z; d[60] = v.w;
            }
        }
        __syncthreads();
        // compute: thread (w, jj, bg): j = bl*8+jj, gates 0..3, b = bg*4..+3,
        // k in [w*128, +128)
        ull acc[4][2];
#pragma unroll
        for (int g = 0; g < 4; g++) { acc[g][0] = 0ull; acc[g][1] = 0ull; }
        const float4* up = up_s + w * 128 * 8 + jj;
        const float*  hp = hs + w * 128 * 20 + bg * 4;
#pragma unroll 8
        for (int kk = 0; kk < 128; kk++) {
            float4 u  = up[kk * 8];
            float4 hv = *(const float4*)(hp + kk * 20);
            ull h2a = ((ull*)&hv)[0], h2b = ((ull*)&hv)[1];
            ull a0 = dupf(u.x), a1 = dupf(u.y), a2 = dupf(u.z), a3 = dupf(u.w);
            FMA2(acc[0][0], a0, h2a); FMA2(acc[0][1], a0, h2b);
            FMA2(acc[1][0], a1, h2a); FMA2(acc[1][1], a1, h2b);
            FMA2(acc[2][0], a2, h2a); FMA2(acc[2][1], a2, h2b);
            FMA2(acc[3][0], a3, h2a); FMA2(acc[3][1], a3, h2b);
        }
        // partials -> red[w][b][jj] as gate-float4
        {
            float2 p[4][2];
#pragma unroll
            for (int g = 0; g < 4; g++) { p[g][0] = u2f(acc[g][0]); p[g][1] = u2f(acc[g][1]); }
#pragma unroll
            for (int i = 0; i < 4; i++) {
                int b = bg * 4 + i;
                float4 zv;
                zv.x = (i & 1) ? p[0][i >> 1].y : p[0][i >> 1].x;
                zv.y = (i & 1) ? p[1][i >> 1].y : p[1][i >> 1].x;
                zv.z = (i & 1) ? p[2][i >> 1].y : p[2][i >> 1].x;
                zv.w = (i & 1) ? p[3][i >> 1].y : p[3][i >> 1].x;
                red[(w * 16 + b) * 8 + jj] = zv;
            }
        }
        __syncthreads();
        // reduce over 8 k-chunks + gates; threads tid<128, identity (bR, jR)
        if (tid < 128) {
            float z0 = xw[0], z1 = xw[1], z2 = xw[2], z3 = xw[3];
#pragma unroll
            for (int q = 0; q < 8; q++) {
                float4 r = red[(q * 16 + bR) * 8 + jR];
                z0 += r.x; z1 += r.y; z2 += r.z; z3 += r.w;
            }
            float i_ = 1.f / (1.f + expf(-z0));
            float f_ = 1.f / (1.f + expf(-z1));
            float o_ = 1.f / (1.f + expf(-z3));
            creg = f_ * creg + i_ * tanhf(z2);
            float hn = o_ * tanhf(creg);
            __stcg(&g_h[(t + 1) & 1][bR * 1024 + jRg], hn);
            __stcg(&H[(size_t)(t * 16 + bR) * 1024 + jRg], hn);
        }
        gbar();
    }
}

// ---------------------------------------------------------------------------
extern "C" void kernel_launch(void* const* d_in, const int* in_sizes, int n_in,
                              void* d_out, int out_size)
{
    const int*   seq  = (const int*)  d_in[0];
    const float* emb  = (const float*)d_in[1];
    const float* W0   = (const float*)d_in[2];
    const float* U0   = (const float*)d_in[3];
    const float* b0   = (const float*)d_in[4];
    const float* W1   = (const float*)d_in[5];
    const float* U1   = (const float*)d_in[6];
    const float* b1   = (const float*)d_in[7];
    const float* Wout = (const float*)d_in[8];
    const float* bout = (const float*)d_in[9];
    float* out = (float*)d_out;

    float *XW, *H, *Up0, *Up1;
    cudaGetSymbolAddress((void**)&XW,  g_XW);
    cudaGetSymbolAddress((void**)&H,   g_H);
    cudaGetSymbolAddress((void**)&Up0, g_Up0);
    cudaGetSymbolAddress((void**)&Up1, g_Up1);

    cudaFuncSetAttribute(lstm_fused, cudaFuncAttributeMaxDynamicSharedMemorySize, SMEM_LSTM);

    repack<<<4096, 256>>>(U0, Up0);
    repack<<<4096, 256>>>(U1, Up1);

    gemm<<<dim3(32, 32), 256>>>(nullptr, W0, b0, XW, 4096, 1, 0, seq, emb);
    lstm_fused<<<128, 256, SMEM_LSTM>>>((const float4*)Up0, XW, H);
    gemm<<<dim3(32, 32), 256>>>(H, W1, b1, XW, 4096, 0, 0, nullptr, nullptr);
    lstm_fused<<<128, 256, SMEM_LSTM>>>((const float4*)Up1, XW, H);
    gemm<<<dim3(32, 250), 256>>>(H, Wout, bout, out, 32000, 0, 1, nullptr, nullptr);
}

// round 15
// speedup vs baseline: 1.1672x; 1.0834x over previous
#include <cuda_runtime.h>
#include <cuda_bf16.h>
#include <math.h>
#include <stdint.h>

typedef unsigned long long ull;
#define FMA2(acc, a, b) asm("fma.rn.f32x2 %0, %1, %2, %0;" : "+l"(acc) : "l"(a), "l"(b))
__device__ __forceinline__ ull dupf(float x) { ull r; asm("mov.b64 %0, {%1, %1};" : "=l"(r) : "f"(x)); return r; }
__device__ __forceinline__ float2 u2f(ull v) { float2 r; asm("mov.b64 {%0, %1}, %2;" : "=f"(r.x), "=f"(r.y) : "l"(v)); return r; }
__device__ __forceinline__ uint32_t s2u(const void* p) {
    uint32_t a;
    asm("{.reg .u64 t; cvta.to.shared.u64 t, %1; cvt.u32.u64 %0, t;}" : "=r"(a) : "l"(p));
    return a;
}

// device-global scratch
__device__ float g_XW [(size_t)4096 * 4096];
__device__ float g_H  [(size_t)4096 * 1024];
__device__ float g_At [(size_t)1024 * 4096];
__device__ float g_Up0[(size_t)1024 * 4096];
__device__ float g_Up1[(size_t)1024 * 4096];
__device__ float g_h  [2][16 * 1024];
__device__ unsigned g_cnt, g_gen;

// Up[k][j][g] = U[k][g*1024+j]
__global__ void repack(const float* __restrict__ U, float* __restrict__ Up) {
    int i = blockIdx.x * 256 + threadIdx.x;
    int k = i >> 10, j = i & 1023;
    float4 v = { U[(size_t)k*4096 + j],        U[(size_t)k*4096 + 1024 + j],
                 U[(size_t)k*4096 + 2048 + j], U[(size_t)k*4096 + 3072 + j] };
    ((float4*)Up)[(size_t)k*1024 + j] = v;
}

// At[k][s] = emb[seq[s%16, s/16]][k] * 32  (gather + transpose)
__global__ void tX(const int* __restrict__ seq, const float* __restrict__ emb,
                   float* __restrict__ At) {
    __shared__ float t[32][33];
    int sb = blockIdx.x * 32, kb = blockIdx.y * 32;
    int x = threadIdx.x, y = threadIdx.y;            // (32, 8)
#pragma unroll
    for (int i = 0; i < 4; i++) {
        int s = sb + y + 8 * i;
        int tok = seq[(s & 15) * 256 + (s >> 4)];
        t[y + 8*i][x] = emb[(size_t)tok * 1024 + kb + x] * 32.f;
    }
    __syncthreads();
#pragma unroll
    for (int i = 0; i < 4; i++)
        At[(size_t)(kb + y + 8*i) * 4096 + sb + x] = t[x][y + 8*i];
}

// At[k][s] = H[s][k]  (transpose)
__global__ void tH(const float* __restrict__ H, float* __restrict__ At) {
    __shared__ float t[32][33];
    int sb = blockIdx.x * 32, kb = blockIdx.y * 32;
    int x = threadIdx.x, y = threadIdx.y;            // (32, 8)
#pragma unroll
    for (int i = 0; i < 4; i++)
        t[y + 8*i][x] = H[(size_t)(sb + y + 8*i) * 1024 + kb + x];
    __syncthreads();
#pragma unroll
    for (int i = 0; i < 4; i++)
        At[(size_t)(kb + y + 8*i) * 4096 + sb + x] = t[x][y + 8*i];
}

// pipelined f32x2 GEMM: C[4096, N] = At^T @ Bm + bias, 2-stage cp.async.
// cmode1: row s -> out[(s%16)*256 + s/16] remap.
__global__ __launch_bounds__(256, 2)
void gemm2(const float* __restrict__ At, const float* __restrict__ Bm,
           const float* __restrict__ bias, float* __restrict__ C,
           int N, int cmode)
{
    __shared__ float As[2][16][128];
    __shared__ float Bs[2][16][128];
    const int tid = threadIdx.x;
    const int m0 = blockIdx.x * 128, n0 = blockIdx.y * 128;
    const int ty = tid >> 4, tx = tid & 15;
    const int kk0 = tid >> 5, seg0 = tid & 31;
    const int kk1 = (tid + 256) >> 5, seg1 = tid & 31;

    ull acc[8][4];
#pragma unroll
    for (int i = 0; i < 8; i++)
#pragma unroll
        for (int j = 0; j < 4; j++) acc[i][j] = 0ull;

    auto issue = [&](int st, int k0) {
        uint32_t da0 = s2u(&As[st][kk0][seg0 * 4]);
        uint32_t da1 = s2u(&As[st][kk1][seg1 * 4]);
        uint32_t db0 = s2u(&Bs[st][kk0][seg0 * 4]);
        uint32_t db1 = s2u(&Bs[st][kk1][seg1 * 4]);
        const void* sa0 = At + (size_t)(k0 + kk0) * 4096 + m0 + seg0 * 4;
        const void* sa1 = At + (size_t)(k0 + kk1) * 4096 + m0 + seg1 * 4;
        const void* sb0 = Bm + (size_t)(k0 + kk0) * N + n0 + seg0 * 4;
        const void* sb1 = Bm + (size_t)(k0 + kk1) * N + n0 + seg1 * 4;
        asm volatile("cp.async.cg.shared.global [%0], [%1], 16;" :: "r"(da0), "l"(sa0));
        asm volatile("cp.async.cg.shared.global [%0], [%1], 16;" :: "r"(da1), "l"(sa1));
        asm volatile("cp.async.cg.shared.global [%0], [%1], 16;" :: "r"(db0), "l"(sb0));
        asm volatile("cp.async.cg.shared.global [%0], [%1], 16;" :: "r"(db1), "l"(sb1));
        asm volatile("cp.async.commit_group;");
    };

    issue(0, 0);
    for (int it = 0; it < 64; it++) {
        if (it < 63) {
            issue((it + 1) & 1, (it + 1) * 16);
            asm volatile("cp.async.wait_group 1;");
        } else {
            asm volatile("cp.async.wait_group 0;");
        }
        __syncthreads();
        const int st = it & 1;
#pragma unroll
        for (int kk = 0; kk < 16; kk++) {
            float ra[8]; ull rb[4];
            *(float4*)ra       = *(float4*)&As[st][kk][ty * 8];
            *(float4*)(ra + 4) = *(float4*)&As[st][kk][ty * 8 + 4];
            float4 b0_ = *(float4*)&Bs[st][kk][tx * 8];
            float4 b1_ = *(float4*)&Bs[st][kk][tx * 8 + 4];
            rb[0] = ((ull*)&b0_)[0]; rb[1] = ((ull*)&b0_)[1];
            rb[2] = ((ull*)&b1_)[0]; rb[3] = ((ull*)&b1_)[1];
#pragma unroll
            for (int i = 0; i < 8; i++) {
                ull a2 = dupf(ra[i]);
                FMA2(acc[i][0], a2, rb[0]); FMA2(acc[i][1], a2, rb[1]);
                FMA2(acc[i][2], a2, rb[2]); FMA2(acc[i][3], a2, rb[3]);
            }
        }
        __syncthreads();
    }
    float bi[8];
#pragma unroll
    for (int j = 0; j < 8; j++) bi[j] = bias[n0 + tx * 8 + j];
#pragma unroll
    for (int i = 0; i < 8; i++) {
        int s = m0 + ty * 8 + i;
        size_t off = cmode
            ? (size_t)(s & 15) * 8192000u + (size_t)(s >> 4) * 32000u + n0 + tx * 8
            : (size_t)s * N + n0 + tx * 8;
        float c_[8];
#pragma unroll
        for (int jp = 0; jp < 4; jp++) {
            float2 v = u2f(acc[i][jp]);
            c_[jp*2] = v.x + bi[jp*2]; c_[jp*2+1] = v.y + bi[jp*2+1];
        }
        *(float4*)(C + off)     = *(float4*)c_;
        *(float4*)(C + off + 4) = *(float4*)(c_ + 4);
    }
}

// grid barrier
#define NBLK 128u
__device__ __forceinline__ void gbar() {
    __syncthreads();
    if (threadIdx.x == 0) {
        unsigned gen, a;
        asm volatile("ld.acquire.gpu.global.u32 %0, [%1];" : "=r"(gen) : "l"(&g_gen));
        asm volatile("atom.release.gpu.global.add.u32 %0, [%1], %2;"
                     : "=r"(a) : "l"(&g_cnt), "r"(1u));
        if (a == NBLK - 1u) {
            asm volatile("st.relaxed.gpu.global.u32 [%0], %1;" :: "l"(&g_cnt), "r"(0u));
            asm volatile("red.release.gpu.global.add.u32 [%0], %1;" :: "l"(&g_gen), "r"(1u));
        } else {
            unsigned c;
            do { asm volatile("ld.acquire.gpu.global.u32 %0, [%1];" : "=r"(c) : "l"(&g_gen)); }
            while (c == gen);
        }
    }
    __syncthreads();
}

// fused persistent LSTM layer (proven)
#define SM_UP 0
#define SM_HS 131072
#define SM_RED (131072 + 81920)
#define SMEM_LSTM (131072 + 81920 + 16384)
__global__ __launch_bounds__(256, 1)
void lstm_fused(const float4* __restrict__ Up, const float* __restrict__ XW,
                float* __restrict__ H)
{
    extern __shared__ char sm_[];
    float4* up_s = (float4*)(sm_ + SM_UP);
    float*  hs   = (float*) (sm_ + SM_HS);
    float4* red  = (float4*)(sm_ + SM_RED);

    const int tid = threadIdx.x, bl = blockIdx.x;
    const int w = tid >> 5, lane = tid & 31;
    const int jj = (tid & 31) >> 2, bg = tid & 3;
    const int sbB = lane >> 1, kg = lane & 1;
    const int bR = (tid & 127) >> 3, jR = tid & 7;
    const int jRg = bl * 8 + jR;

    {
        const float4* up = Up + bl * 8;
#pragma unroll 8
        for (int i = tid; i < 8192; i += 256)
            up_s[i] = up[(size_t)(i >> 3) * 1024 + (i & 7)];
    }
    if (tid < 128) g_h[0][bl * 128 + tid] = 0.f;
    float creg = 0.f;
    gbar();

    for (int t = 0; t < 256; t++) {
        float xw[4];
        if (tid < 128) {
            const float* xp = XW + (size_t)(t * 16 + bR) * 4096 + jRg;
#pragma unroll
            for (int g = 0; g < 4; g++) xw[g] = __ldcg(xp + g * 1024);
        }
        {
            const float4* hsrc = (const float4*)g_h[t & 1] + sbB * 256;
#pragma unroll
            for (int i = 0; i < 16; i++) {
                int k4 = i * 16 + w * 2 + kg;
                float4 v = __ldcg(hsrc + k4);
                float* d = hs + (k4 * 4) * 20 + sbB;
                d[0] = v.x; d[20] = v.y; d[40] = v.z; d[60] = v.w;
            }
        }
        __syncthreads();
        ull acc[4][2];
#pragma unroll
        for (int g = 0; g < 4; g++) { acc[g][0] = 0ull; acc[g][1] = 0ull; }
        const float4* up = up_s + w * 128 * 8 + jj;
        const float*  hp = hs + w * 128 * 20 + bg * 4;
#pragma unroll 8
        for (int kk = 0; kk < 128; kk++) {
            float4 u  = up[kk * 8];
            float4 hv = *(const float4*)(hp + kk * 20);
            ull h2a = ((ull*)&hv)[0], h2b = ((ull*)&hv)[1];
            ull a0 = dupf(u.x), a1 = dupf(u.y), a2 = dupf(u.z), a3 = dupf(u.w);
            FMA2(acc[0][0], a0, h2a); FMA2(acc[0][1], a0, h2b);
            FMA2(acc[1][0], a1, h2a); FMA2(acc[1][1], a1, h2b);
            FMA2(acc[2][0], a2, h2a); FMA2(acc[2][1], a2, h2b);
            FMA2(acc[3][0], a3, h2a); FMA2(acc[3][1], a3, h2b);
        }
        {
            float2 p[4][2];
#pragma unroll
            for (int g = 0; g < 4; g++) { p[g][0] = u2f(acc[g][0]); p[g][1] = u2f(acc[g][1]); }
#pragma unroll
            for (int i = 0; i < 4; i++) {
                int b = bg * 4 + i;
                float4 zv;
                zv.x = (i & 1) ? p[0][i >> 1].y : p[0][i >> 1].x;
                zv.y = (i & 1) ? p[1][i >> 1].y : p[1][i >> 1].x;
                zv.z = (i & 1) ? p[2][i >> 1].y : p[2][i >> 1].x;
                zv.w = (i & 1) ? p[3][i >> 1].y : p[3][i >> 1].x;
                red[(w * 16 + b) * 8 + jj] = zv;
            }
        }
        __syncthreads();
        if (tid < 128) {
            float z0 = xw[0], z1 = xw[1], z2 = xw[2], z3 = xw[3];
#pragma unroll
            for (int q = 0; q < 8; q++) {
                float4 r = red[(q * 16 + bR) * 8 + jR];
                z0 += r.x; z1 += r.y; z2 += r.z; z3 += r.w;
            }
            float i_ = 1.f / (1.f + expf(-z0));
            float f_ = 1.f / (1.f + expf(-z1));
            float o_ = 1.f / (1.f + expf(-z3));
            creg = f_ * creg + i_ * tanhf(z2);
            float hn = o_ * tanhf(creg);
            __stcg(&g_h[(t + 1) & 1][bR * 1024 + jRg], hn);
            __stcg(&H[(size_t)(t * 16 + bR) * 1024 + jRg], hn);
        }
        gbar();
    }
}

extern "C" void kernel_launch(void* const* d_in, const int* in_sizes, int n_in,
                              void* d_out, int out_size)
{
    const int*   seq  = (const int*)  d_in[0];
    const float* emb  = (const float*)d_in[1];
    const float* W0   = (const float*)d_in[2];
    const float* U0   = (const float*)d_in[3];
    const float* b0   = (const float*)d_in[4];
    const float* W1   = (const float*)d_in[5];
    const float* U1   = (const float*)d_in[6];
    const float* b1   = (const float*)d_in[7];
    const float* Wout = (const float*)d_in[8];
    const float* bout = (const float*)d_in[9];
    float* out = (float*)d_out;

    float *XW, *H, *At, *Up0, *Up1;
    cudaGetSymbolAddress((void**)&XW,  g_XW);
    cudaGetSymbolAddress((void**)&H,   g_H);
    cudaGetSymbolAddress((void**)&At,  g_At);
    cudaGetSymbolAddress((void**)&Up0, g_Up0);
    cudaGetSymbolAddress((void**)&Up1, g_Up1);

    cudaFuncSetAttribute(lstm_fused, cudaFuncAttributeMaxDynamicSharedMemorySize, SMEM_LSTM);

    repack<<<4096, 256>>>(U0, Up0);
    repack<<<4096, 256>>>(U1, Up1);

    tX<<<dim3(128, 32), dim3(32, 8)>>>(seq, emb, At);
    gemm2<<<dim3(32, 32), 256>>>(At, W0, b0, XW, 4096, 0);
    lstm_fused<<<128, 256, SMEM_LSTM>>>((const float4*)Up0, XW, H);

    tH<<<dim3(128, 32), dim3(32, 8)>>>(H, At);
    gemm2<<<dim3(32, 32), 256>>>(At, W1, b1, XW, 4096, 0);
    lstm_fused<<<128, 256, SMEM_LSTM>>>((const float4*)Up1, XW, H);

    tH<<<dim3(128, 32), dim3(32, 8)>>>(H, At);
    gemm2<<<dim3(32, 250), 256>>>(At, Wout, bout, out, 32000, 1);
}

// round 16
// speedup vs baseline: 1.2626x; 1.0817x over previous
#include <cuda_runtime.h>
#include <cuda_bf16.h>
#include <math.h>
#include <stdint.h>

typedef unsigned long long ull;
#define FMA2(acc, a, b) asm("fma.rn.f32x2 %0, %1, %2, %0;" : "+l"(acc) : "l"(a), "l"(b))
__device__ __forceinline__ ull dupf(float x) { ull r; asm("mov.b64 %0, {%1, %1};" : "=l"(r) : "f"(x)); return r; }
__device__ __forceinline__ float2 u2f(ull v) { float2 r; asm("mov.b64 {%0, %1}, %2;" : "=f"(r.x), "=f"(r.y) : "l"(v)); return r; }
__device__ __forceinline__ uint32_t s2u(const void* p) {
    uint32_t a;
    asm("{.reg .u64 t; cvta.to.shared.u64 t, %1; cvt.u32.u64 %0, t;}" : "=r"(a) : "l"(p));
    return a;
}

// device-global scratch
__device__ float g_XW [(size_t)4096 * 4096];
__device__ float g_H  [(size_t)4096 * 1024];
__device__ float g_At [(size_t)1024 * 4096];
__device__ float g_Up0[(size_t)1024 * 4096];
__device__ float g_Up1[(size_t)1024 * 4096];
__device__ float g_h  [2][16 * 1024];
__device__ unsigned g_cnt, g_gen;

// Up[k][j][g] = U[k][g*1024+j]
__global__ void repack(const float* __restrict__ U, float* __restrict__ Up) {
    int i = blockIdx.x * 256 + threadIdx.x;
    int k = i >> 10, j = i & 1023;
    float4 v = { U[(size_t)k*4096 + j],        U[(size_t)k*4096 + 1024 + j],
                 U[(size_t)k*4096 + 2048 + j], U[(size_t)k*4096 + 3072 + j] };
    ((float4*)Up)[(size_t)k*1024 + j] = v;
}

// At[k][s] = emb[seq[s%16, s/16]][k] * 32  (gather + transpose)
__global__ void tX(const int* __restrict__ seq, const float* __restrict__ emb,
                   float* __restrict__ At) {
    __shared__ float t[32][33];
    int sb = blockIdx.x * 32, kb = blockIdx.y * 32;
    int x = threadIdx.x, y = threadIdx.y;            // (32, 8)
#pragma unroll
    for (int i = 0; i < 4; i++) {
        int s = sb + y + 8 * i;
        int tok = seq[(s & 15) * 256 + (s >> 4)];
        t[y + 8*i][x] = emb[(size_t)tok * 1024 + kb + x] * 32.f;
    }
    __syncthreads();
#pragma unroll
    for (int i = 0; i < 4; i++)
        At[(size_t)(kb + y + 8*i) * 4096 + sb + x] = t[x][y + 8*i];
}

// At[k][s] = H[s][k]  (transpose)
__global__ void tH(const float* __restrict__ H, float* __restrict__ At) {
    __shared__ float t[32][33];
    int sb = blockIdx.x * 32, kb = blockIdx.y * 32;
    int x = threadIdx.x, y = threadIdx.y;            // (32, 8)
#pragma unroll
    for (int i = 0; i < 4; i++)
        t[y + 8*i][x] = H[(size_t)(sb + y + 8*i) * 1024 + kb + x];
    __syncthreads();
#pragma unroll
    for (int i = 0; i < 4; i++)
        At[(size_t)(kb + y + 8*i) * 4096 + sb + x] = t[x][y + 8*i];
}

// pipelined f32x2 GEMM: C[4096, N] = At^T @ Bm + bias, 2-stage cp.async.
// Conflict-free lane map: warp tile 32m x 64n, lane (lm=lane>>3, ln=lane&7);
// thread owns rows wm+lm*8..+8, cols {wn+ln*4..+4, wn+32+ln*4..+4}.
// cmode1: row s -> out[(s%16)*256 + s/16] remap.
__global__ __launch_bounds__(256, 2)
void gemm2(const float* __restrict__ At, const float* __restrict__ Bm,
           const float* __restrict__ bias, float* __restrict__ C,
           int N, int cmode)
{
    __shared__ float As[2][16][128];
    __shared__ float Bs[2][16][128];
    const int tid = threadIdx.x, lane = tid & 31, wid = tid >> 5;
    const int m0 = blockIdx.x * 128, n0 = blockIdx.y * 128;
    const int wm = (wid & 3) * 32, wn = (wid >> 2) * 64;
    const int lm = lane >> 3, ln = lane & 7;
    const int ar = wm + lm * 8;          // A row group within tile
    const int bc = wn + ln * 4;          // B col group within tile
    const int kk0 = tid >> 5, seg0 = tid & 31;
    const int kk1 = (tid + 256) >> 5, seg1 = tid & 31;

    ull acc[8][4];
#pragma unroll
    for (int i = 0; i < 8; i++)
#pragma unroll
        for (int j = 0; j < 4; j++) acc[i][j] = 0ull;

    auto issue = [&](int st, int k0) {
        uint32_t da0 = s2u(&As[st][kk0][seg0 * 4]);
        uint32_t da1 = s2u(&As[st][kk1][seg1 * 4]);
        uint32_t db0 = s2u(&Bs[st][kk0][seg0 * 4]);
        uint32_t db1 = s2u(&Bs[st][kk1][seg1 * 4]);
        const void* sa0 = At + (size_t)(k0 + kk0) * 4096 + m0 + seg0 * 4;
        const void* sa1 = At + (size_t)(k0 + kk1) * 4096 + m0 + seg1 * 4;
        const void* sb0 = Bm + (size_t)(k0 + kk0) * N + n0 + seg0 * 4;
        const void* sb1 = Bm + (size_t)(k0 + kk1) * N + n0 + seg1 * 4;
        asm volatile("cp.async.cg.shared.global [%0], [%1], 16;" :: "r"(da0), "l"(sa0));
        asm volatile("cp.async.cg.shared.global [%0], [%1], 16;" :: "r"(da1), "l"(sa1));
        asm volatile("cp.async.cg.shared.global [%0], [%1], 16;" :: "r"(db0), "l"(sb0));
        asm volatile("cp.async.cg.shared.global [%0], [%1], 16;" :: "r"(db1), "l"(sb1));
        asm volatile("cp.async.commit_group;");
    };

    issue(0, 0);
    for (int it = 0; it < 64; it++) {
        if (it < 63) {
            issue((it + 1) & 1, (it + 1) * 16);
            asm volatile("cp.async.wait_group 1;");
        } else {
            asm volatile("cp.async.wait_group 0;");
        }
        __syncthreads();
        const int st = it & 1;
#pragma unroll
        for (int kk = 0; kk < 16; kk++) {
            float ra[8]; ull rb[4];
            *(float4*)ra       = *(float4*)&As[st][kk][ar];
            *(float4*)(ra + 4) = *(float4*)&As[st][kk][ar + 4];
            float4 b0_ = *(float4*)&Bs[st][kk][bc];
            float4 b1_ = *(float4*)&Bs[st][kk][bc + 32];
            rb[0] = ((ull*)&b0_)[0]; rb[1] = ((ull*)&b0_)[1];
            rb[2] = ((ull*)&b1_)[0]; rb[3] = ((ull*)&b1_)[1];
#pragma unroll
            for (int i = 0; i < 8; i++) {
                ull a2 = dupf(ra[i]);
                FMA2(acc[i][0], a2, rb[0]); FMA2(acc[i][1], a2, rb[1]);
                FMA2(acc[i][2], a2, rb[2]); FMA2(acc[i][3], a2, rb[3]);
            }
        }
        __syncthreads();
    }
    float bi0[4], bi1[4];
#pragma unroll
    for (int j = 0; j < 4; j++) {
        bi0[j] = bias[n0 + bc + j];
        bi1[j] = bias[n0 + bc + 32 + j];
    }
#pragma unroll
    for (int i = 0; i < 8; i++) {
        int s = m0 + ar + i;
        size_t base = cmode
            ? (size_t)(s & 15) * 8192000u + (size_t)(s >> 4) * 32000u
            : (size_t)s * N;
        float2 v0 = u2f(acc[i][0]), v1 = u2f(acc[i][1]);
        float2 v2 = u2f(acc[i][2]), v3 = u2f(acc[i][3]);
        float4 c0 = { v0.x + bi0[0], v0.y + bi0[1], v1.x + bi0[2], v1.y + bi0[3] };
        float4 c1 = { v2.x + bi1[0], v2.y + bi1[1], v3.x + bi1[2], v3.y + bi1[3] };
        *(float4*)(C + base + n0 + bc)      = c0;
        *(float4*)(C + base + n0 + bc + 32) = c1;
    }
}

// grid barrier
#define NBLK 128u
__device__ __forceinline__ void gbar() {
    __syncthreads();
    if (threadIdx.x == 0) {
        unsigned gen, a;
        asm volatile("ld.acquire.gpu.global.u32 %0, [%1];" : "=r"(gen) : "l"(&g_gen));
        asm volatile("atom.release.gpu.global.add.u32 %0, [%1], %2;"
                     : "=r"(a) : "l"(&g_cnt), "r"(1u));
        if (a == NBLK - 1u) {
            asm volatile("st.relaxed.gpu.global.u32 [%0], %1;" :: "l"(&g_cnt), "r"(0u));
            asm volatile("red.release.gpu.global.add.u32 [%0], %1;" :: "l"(&g_gen), "r"(1u));
        } else {
            unsigned c;
            do { asm volatile("ld.acquire.gpu.global.u32 %0, [%1];" : "=r"(c) : "l"(&g_gen)); }
            while (c == gen);
        }
    }
    __syncthreads();
}

// fused persistent LSTM layer (proven)
#define SM_UP 0
#define SM_HS 131072
#define SM_RED (131072 + 81920)
#define SMEM_LSTM (131072 + 81920 + 16384)
__global__ __launch_bounds__(256, 1)
void lstm_fused(const float4* __restrict__ Up, const float* __restrict__ XW,
                float* __restrict__ H)
{
    extern __shared__ char sm_[];
    float4* up_s = (float4*)(sm_ + SM_UP);
    float*  hs   = (float*) (sm_ + SM_HS);
    float4* red  = (float4*)(sm_ + SM_RED);

    const int tid = threadIdx.x, bl = blockIdx.x;
    const int w = tid >> 5, lane = tid & 31;
    const int jj = (tid & 31) >> 2, bg = tid & 3;
    const int sbB = lane >> 1, kg = lane & 1;
    const int bR = (tid & 127) >> 3, jR = tid & 7;
    const int jRg = bl * 8 + jR;

    {
        const float4* up = Up + bl * 8;
#pragma unroll 8
        for (int i = tid; i < 8192; i += 256)
            up_s[i] = up[(size_t)(i >> 3) * 1024 + (i & 7)];
    }
    if (tid < 128) g_h[0][bl * 128 + tid] = 0.f;
    float creg = 0.f;
    gbar();

    for (int t = 0; t < 256; t++) {
        float xw[4];
        if (tid < 128) {
            const float* xp = XW + (size_t)(t * 16 + bR) * 4096 + jRg;
#pragma unroll
            for (int g = 0; g < 4; g++) xw[g] = __ldcg(xp + g * 1024);
        }
        {
            const float4* hsrc = (const float4*)g_h[t & 1] + sbB * 256;
#pragma unroll
            for (int i = 0; i < 16; i++) {
                int k4 = i * 16 + w * 2 + kg;
                float4 v = __ldcg(hsrc + k4);
                float* d = hs + (k4 * 4) * 20 + sbB;
                d[0] = v.x; d[20] = v.y; d[40] = v.z; d[60] = v.w;
            }
        }
        __syncthreads();
        ull acc[4][2];
#pragma unroll
        for (int g = 0; g < 4; g++) { acc[g][0] = 0ull; acc[g][1] = 0ull; }
        const float4* up = up_s + w * 128 * 8 + jj;
        const float*  hp = hs + w * 128 * 20 + bg * 4;
#pragma unroll 8
        for (int kk = 0; kk < 128; kk++) {
            float4 u  = up[kk * 8];
            float4 hv = *(const float4*)(hp + kk * 20);
            ull h2a = ((ull*)&hv)[0], h2b = ((ull*)&hv)[1];
            ull a0 = dupf(u.x), a1 = dupf(u.y), a2 = dupf(u.z), a3 = dupf(u.w);
            FMA2(acc[0][0], a0, h2a); FMA2(acc[0][1], a0, h2b);
            FMA2(acc[1][0], a1, h2a); FMA2(acc[1][1], a1, h2b);
            FMA2(acc[2][0], a2, h2a); FMA2(acc[2][1], a2, h2b);
            FMA2(acc[3][0], a3, h2a); FMA2(acc[3][1], a3, h2b);
        }
        {
            float2 p[4][2];
#pragma unroll
            for (int g = 0; g < 4; g++) { p[g][0] = u2f(acc[g][0]); p[g][1] = u2f(acc[g][1]); }
#pragma unroll
            for (int i = 0; i < 4; i++) {
                int b = bg * 4 + i;
                float4 zv;
                zv.x = (i & 1) ? p[0][i >> 1].y : p[0][i >> 1].x;
                zv.y = (i & 1) ? p[1][i >> 1].y : p[1][i >> 1].x;
                zv.z = (i & 1) ? p[2][i >> 1].y : p[2][i >> 1].x;
                zv.w = (i & 1) ? p[3][i >> 1].y : p[3][i >> 1].x;
                red[(w * 16 + b) * 8 + jj] = zv;
            }
        }
        __syncthreads();
        if (tid < 128) {
            float z0 = xw[0], z1 = xw[1], z2 = xw[2], z3 = xw[3];
#pragma unroll
            for (int q = 0; q < 8; q++) {
                float4 r = red[(q * 16 + bR) * 8 + jR];
                z0 += r.x; z1 += r.y; z2 += r.z; z3 += r.w;
            }
            float i_ = 1.f / (1.f + expf(-z0));
            float f_ = 1.f / (1.f + expf(-z1));
            float o_ = 1.f / (1.f + expf(-z3));
            creg = f_ * creg + i_ * tanhf(z2);
            float hn = o_ * tanhf(creg);
            __stcg(&g_h[(t + 1) & 1][bR * 1024 + jRg], hn);
            __stcg(&H[(size_t)(t * 16 + bR) * 1024 + jRg], hn);
        }
        gbar();
    }
}

extern "C" void kernel_launch(void* const* d_in, const int* in_sizes, int n_in,
                              void* d_out, int out_size)
{
    const int*   seq  = (const int*)  d_in[0];
    const float* emb  = (const float*)d_in[1];
    const float* W0   = (const float*)d_in[2];
    const float* U0   = (const float*)d_in[3];
    const float* b0   = (const float*)d_in[4];
    const float* W1   = (const float*)d_in[5];
    const float* U1   = (const float*)d_in[6];
    const float* b1   = (const float*)d_in[7];
    const float* Wout = (const float*)d_in[8];
    const float* bout = (const float*)d_in[9];
    float* out = (float*)d_out;

    float *XW, *H, *At, *Up0, *Up1;
    cudaGetSymbolAddress((void**)&XW,  g_XW);
    cudaGetSymbolAddress((void**)&H,   g_H);
    cudaGetSymbolAddress((void**)&At,  g_At);
    cudaGetSymbolAddress((void**)&Up0, g_Up0);
    cudaGetSymbolAddress((void**)&Up1, g_Up1);

    cudaFuncSetAttribute(lstm_fused, cudaFuncAttributeMaxDynamicSharedMemorySize, SMEM_LSTM);

    repack<<<4096, 256>>>(U0, Up0);
    repack<<<4096, 256>>>(U1, Up1);

    tX<<<dim3(128, 32), dim3(32, 8)>>>(seq, emb, At);
    gemm2<<<dim3(32, 32), 256>>>(At, W0, b0, XW, 4096, 0);
    lstm_fused<<<128, 256, SMEM_LSTM>>>((const float4*)Up0, XW, H);

    tH<<<dim3(128, 32), dim3(32, 8)>>>(H, At);
    gemm2<<<dim3(32, 32), 256>>>(At, W1, b1, XW, 4096, 0);
    lstm_fused<<<128, 256, SMEM_LSTM>>>((const float4*)Up1, XW, H);

    tH<<<dim3(128, 32), dim3(32, 8)>>>(H, At);
    gemm2<<<dim3(32, 250), 256>>>(At, Wout, bout, out, 32000, 1);
}